// round 15
// baseline (speedup 1.0000x reference)
#include <cuda_runtime.h>
#include <cuda_fp16.h>
#include <cstdint>

// Problem constants
#define Bb 32
#define Tt 2048
#define Cc 1024
#define Hh 64
#define BT (Bb * Tt)

// 0.125 (= H^-0.5) * log2(e): scores computed directly in base-2 domain
#define QSCALE 0.180336880111227f

// Scratch (__device__ globals; no allocation allowed)
__device__ __half g_Wh[(size_t)Cc * 192];     // [k][n]  n: 0..63 K, 64..127 Q, 128..191 V
__device__ __half g_q[(size_t)BT * Hh];
__device__ __half g_k[(size_t)BT * Hh];
__device__ __half g_v[(size_t)BT * Hh];

// ---------------------------------------------------------------------------
// Helpers
// ---------------------------------------------------------------------------
__device__ __forceinline__ float ex2f(float x) {
    float r;
    asm("ex2.approx.f32 %0, %1;" : "=f"(r) : "f"(x));
    return r;
}

__device__ __forceinline__ uint32_t pk(float a, float b) {
    __half2 h = __floats2half2_rn(a, b);
    return *(uint32_t*)&h;
}

__device__ __forceinline__ uint32_t smem_u32(const void* p) {
    uint32_t a;
    asm("{ .reg .u64 t; cvta.to.shared.u64 t, %1; cvt.u32.u64 %0, t; }" : "=r"(a) : "l"(p));
    return a;
}

#define LDSM4(r, addr) \
    asm volatile("ldmatrix.sync.aligned.m8n8.x4.shared.b16 {%0,%1,%2,%3}, [%4];" \
        : "=r"((r)[0]), "=r"((r)[1]), "=r"((r)[2]), "=r"((r)[3]) : "r"(addr))
#define LDSM4T(r, addr) \
    asm volatile("ldmatrix.sync.aligned.m8n8.x4.trans.shared.b16 {%0,%1,%2,%3}, [%4];" \
        : "=r"((r)[0]), "=r"((r)[1]), "=r"((r)[2]), "=r"((r)[3]) : "r"(addr))
#define MMAH(d, a, b0_, b1_) \
    asm volatile("mma.sync.aligned.m16n8k16.row.col.f32.f16.f16.f32 " \
        "{%0,%1,%2,%3}, {%4,%5,%6,%7}, {%8,%9}, {%0,%1,%2,%3};" \
        : "+f"((d)[0]), "+f"((d)[1]), "+f"((d)[2]), "+f"((d)[3]) \
        : "r"((a)[0]), "r"((a)[1]), "r"((a)[2]), "r"((a)[3]), "r"(b0_), "r"(b1_))
#define CP_ASYNC16(dst, src) \
    asm volatile("cp.async.cg.shared.global [%0], [%1], 16;" :: "r"(dst), "l"(src))
#define CP_COMMIT() asm volatile("cp.async.commit_group;" ::: "memory")
#define CP_WAIT(n)  asm volatile("cp.async.wait_group %0;" :: "n"(n) : "memory")

// ---------------------------------------------------------------------------
// Prep: W -> fp16, Q scale folded, layout [k=1024][n=192]
// ---------------------------------------------------------------------------
__global__ __launch_bounds__(256) void prep_w(
    const float* __restrict__ Wk, const float* __restrict__ Wq, const float* __restrict__ Wv)
{
    const int idx = blockIdx.x * 256 + threadIdx.x;
    const int k = idx / 192, n = idx % 192;
    float f;
    if (n < 64)       f = Wk[k * 64 + n];
    else if (n < 128) f = Wq[k * 64 + (n - 64)] * QSCALE;
    else              f = Wv[k * 64 + (n - 128)];
    g_Wh[idx] = __float2half_rn(f);
}

// ---------------------------------------------------------------------------
// Projection GEMM (EXACT R12 version): fp16, 64x192 CTA tile, 2 CTAs/SM,
// distance-2 x prefetch in registers, W cp.async double-buffered.
// ---------------------------------------------------------------------------
#define SA_BUF   8192
#define SB_OFF   16384
#define SB_BUF   25600
#define BSTRIDE  400
#define PJ_SMEM  67584

#define LDG_X(C0) do { \
    const float* _xs = x + (size_t)row0 * Cc + (C0) + (tid & 15) * 4; \
    _Pragma("unroll") for (int _i = 0; _i < 4; _i++) \
        xr[_i] = *(const float4*)(_xs + (size_t)(_i * 16 + (tid >> 4)) * Cc); \
} while (0)

#define CONVERT_X(P) do { \
    _Pragma("unroll") for (int _i = 0; _i < 4; _i++) { \
        const int _r = _i * 16 + (tid >> 4); \
        const int _c4 = tid & 15; \
        uint2 _hv; \
        _hv.x = pk(xr[_i].x, xr[_i].y); \
        _hv.y = pk(xr[_i].z, xr[_i].w); \
        const uint32_t _off = (uint32_t)(_r * 128 + (((_c4 >> 1) ^ (_r & 7)) << 4) + (_c4 & 1) * 8); \
        *(uint2*)(smp + (P) * SA_BUF + _off) = _hv; \
    } \
} while (0)

#define W_LOAD(C) do { \
    const uint32_t _bw = sb + SB_OFF + ((C) & 1) * SB_BUF; \
    _Pragma("unroll") for (int _i = 0; _i < 6; _i++) { \
        const int _u = _i * 256 + tid; \
        const int _r = _u / 24, _cg = _u % 24; \
        CP_ASYNC16(_bw + _r * BSTRIDE + _cg * 16, \
                   (const char*)(g_Wh + (size_t)((C) * 64 + _r) * 192 + _cg * 8)); \
    } \
    CP_COMMIT(); \
} while (0)

__global__ __launch_bounds__(256, 2) void proj_tc(const float* __restrict__ x)
{
    extern __shared__ char smp[];
    const uint32_t sb = smem_u32(smp);
    const int tid  = threadIdx.x;
    const int wid  = tid >> 5;
    const int lane = tid & 31;
    const int wm   = wid >> 2;
    const int wn   = wid & 3;
    const int row0 = blockIdx.x * 64;

    const int gid = lane >> 2, tig = lane & 3;
    const int lr  = lane & 7,  grp = lane >> 3;

    float acc[2][6][4];
#pragma unroll
    for (int mi = 0; mi < 2; mi++)
#pragma unroll
        for (int j = 0; j < 6; j++)
#pragma unroll
            for (int e = 0; e < 4; e++) acc[mi][j][e] = 0.f;

    int rowA[2];
#pragma unroll
    for (int mi = 0; mi < 2; mi++) rowA[mi] = wm * 32 + mi * 16 + lr + (grp & 1) * 8;
    const int ac16g = grp >> 1;
    const uint32_t bofs = (uint32_t)((lr + (grp & 1) * 8) * BSTRIDE + wn * 96 + (grp >> 1) * 16);

    float4 xr[4];

    LDG_X(0);
    W_LOAD(0);
    CONVERT_X(0);
    LDG_X(64);

    for (int c = 0; c < 16; c++) {
        const int p = c & 1;
        CP_WAIT(0);
        __syncthreads();

        const uint32_t abh  = sb + p * SA_BUF;
        const uint32_t bbuf = sb + SB_OFF + p * SB_BUF;
#pragma unroll
        for (int ks = 0; ks < 4; ks++) {
            uint32_t ah[2][4];
#pragma unroll
            for (int mi = 0; mi < 2; mi++) {
                const int c16 = 2 * ks + ac16g;
                LDSM4(ah[mi], abh + (uint32_t)(rowA[mi] * 128 + ((c16 ^ lr) << 4)));
            }
#pragma unroll
            for (int nt = 0; nt < 3; nt++) {
                uint32_t bh[4];
                LDSM4T(bh, bbuf + bofs + (uint32_t)(ks * 16 * BSTRIDE + nt * 32));
#pragma unroll
                for (int mi = 0; mi < 2; mi++) {
                    MMAH(acc[mi][2 * nt],     ah[mi], bh[0], bh[1]);
                    MMAH(acc[mi][2 * nt + 1], ah[mi], bh[2], bh[3]);
                }
            }
        }

        if (c < 15) {
            W_LOAD(c + 1);
            CONVERT_X(p ^ 1);
        }
        if (c < 14) LDG_X((c + 2) * 64);
    }

#pragma unroll
    for (int mi = 0; mi < 2; mi++) {
        const int r1 = row0 + wm * 32 + mi * 16 + gid;
        const int r2 = r1 + 8;
#pragma unroll
        for (int j = 0; j < 6; j++) {
            const int col = wn * 48 + j * 8 + tig * 2;
            __half* dst; int cc;
            if (col < 64)       { dst = g_k; cc = col; }
            else if (col < 128) { dst = g_q; cc = col - 64; }
            else                { dst = g_v; cc = col - 128; }
            *(uint32_t*)(dst + (size_t)r1 * Hh + cc) = pk(acc[mi][j][0], acc[mi][j][1]);
            *(uint32_t*)(dst + (size_t)r2 * Hh + cc) = pk(acc[mi][j][2], acc[mi][j][3]);
        }
    }
}

// ---------------------------------------------------------------------------
// Flash attention: 64-row q-tiles, 4 warps / 128 threads, NOW 5 CTAs/SM via
// 128B-row XOR-swizzled Q/K/V staging (CTA smem 40KB; 5x40KB = 204.8KB).
// Swizzle: 16B chunk c of row r lives at r*128 + ((c ^ (r&7))<<4); every
// ldmatrix fragment here has row&7 == lane&7, so reads stay conflict-free.
// Compute body identical to R14 (unnormalized softmax, Q in regs, depth-1
// 2-stage KV ring). 20 warps/SM for latency cover.
// ---------------------------------------------------------------------------
#define KV_OFF  8192              // Q: 64 rows x 128B
#define STAGE   16384             // K 8192 + V 8192
#define AT_SMEM 40960             // Q + 2 stages

#define LOAD_KV64(J) do { \
    const int _jn = (J) * 64; \
    const uint32_t _st = sb + KV_OFF + ((J) & 1) * STAGE; \
    _Pragma("unroll") for (int _i = 0; _i < 4; _i++) { \
        const int _idx = _i * 128 + tid; \
        const int _r = _idx >> 3, _cg = _idx & 7; \
        const size_t _g = (size_t)(b * Tt + _jn + _r) * Hh + _cg * 8; \
        const uint32_t _d0 = _st + _r * 128 + (((_cg ^ (_r & 7))) << 4); \
        CP_ASYNC16(_d0,        (const char*)(g_k + _g)); \
        CP_ASYNC16(_d0 + 8192, (const char*)(g_v + _g)); \
    } \
    CP_COMMIT(); \
} while (0)

__global__ __launch_bounds__(128, 5) void attn_tc(float* __restrict__ out)
{
    extern __shared__ char sma[];
    const uint32_t sb  = smem_u32(sma);

    const int tid  = threadIdx.x;
    const int w    = tid >> 5;                       // 0..3
    const int lane = tid & 31;
    const int b    = blockIdx.y;
    const int it   = (Tt / 64 - 1) - blockIdx.x;     // heaviest q-tiles first
    const int q0   = it * 64;
    const int jmax = it;                             // 64-row KV tiles 0..it

    const int gid = lane >> 2, tig = lane & 3;
    const int lr  = lane & 7,  grp = lane >> 3;

    // swizzled ldsm addressing: row&7 == lr for all fragments below
    const uint32_t qro = (uint32_t)((16 * w + lr + (grp & 1) * 8) * 128);
    const uint32_t kro = (uint32_t)((lr + (grp >> 1) * 8) * 128);
    const uint32_t vro = (uint32_t)((lr + (grp & 1) * 8) * 128);
    uint32_t qx[4], kx[4], vx[4];
#pragma unroll
    for (int i = 0; i < 4; i++) {
        qx[i] = (uint32_t)(((2 * i + (grp >> 1)) ^ lr) << 4);
        kx[i] = (uint32_t)(((2 * i + (grp & 1)) ^ lr) << 4);
        vx[i] = (uint32_t)(((2 * i + (grp >> 1)) ^ lr) << 4);
    }

    // ---- prologue: Q + KV(0) in one group ----
#pragma unroll
    for (int i = 0; i < 4; i++) {
        const int idx = i * 128 + tid;               // < 512
        const int r = idx >> 3, cg = idx & 7;
        const uint32_t soff = (uint32_t)(r * 128 + ((cg ^ (r & 7)) << 4));
        CP_ASYNC16(sb + soff,
                   (const char*)(g_q + (size_t)(b * Tt + q0 + r) * Hh + cg * 8));
        const size_t g = (size_t)(b * Tt + r) * Hh + cg * 8;
        CP_ASYNC16(sb + KV_OFF + soff,        (const char*)(g_k + g));
        CP_ASYNC16(sb + KV_OFF + 8192 + soff, (const char*)(g_v + g));
    }
    CP_COMMIT();
    CP_WAIT(0);
    __syncthreads();

    // Q into registers for good
    uint32_t qf[4][4];
#pragma unroll
    for (int ks = 0; ks < 4; ks++) LDSM4(qf[ks], sb + qro + qx[ks]);

    float o[8][4];
#pragma unroll
    for (int nt = 0; nt < 8; nt++)
#pragma unroll
        for (int e = 0; e < 4; e++) o[nt][e] = 0.f;
    float l0 = 0.f, l1 = 0.f;

    const int r1g = q0 + 16 * w + gid;
    const int r2g = r1g + 8;
    const int wlim = q0 + 16 * w + 15;

    for (int jt = 0; jt <= jmax; jt++) {
        if (jt > 0) {
            CP_WAIT(0);              // KV(jt) landed
            __syncthreads();         // everyone done with buffer (jt+1)&1
        }
        if (jt < jmax) LOAD_KV64(jt + 1);

        const int j0 = jt * 64;
        if (j0 <= wlim) {
            const uint32_t buf  = sb + KV_OFF + (jt & 1) * STAGE;
            const uint32_t bufv = buf + 8192;

            // ---- S = Q @ K^T ----
            float s[8][4];
#pragma unroll
            for (int nt = 0; nt < 8; nt++)
#pragma unroll
                for (int e = 0; e < 4; e++) s[nt][e] = 0.f;
#pragma unroll
            for (int ks = 0; ks < 4; ks++) {
#pragma unroll
                for (int np = 0; np < 4; np++) {
                    uint32_t bh[4];
                    LDSM4(bh, buf + kro + (uint32_t)(np * 2048) + kx[ks]);
                    MMAH(s[2 * np],     qf[ks], bh[0], bh[1]);
                    MMAH(s[2 * np + 1], qf[ks], bh[2], bh[3]);
                }
            }

            // ---- causal mask (ex2 flushes -1e30 to 0) ----
            if (j0 + 63 > q0 + 16 * w) {
#pragma unroll
                for (int nt = 0; nt < 8; nt++) {
                    const int cb = j0 + 8 * nt + 2 * tig;
                    if (cb     > r1g) s[nt][0] = -1e30f;
                    if (cb + 1 > r1g) s[nt][1] = -1e30f;
                    if (cb     > r2g) s[nt][2] = -1e30f;
                    if (cb + 1 > r2g) s[nt][3] = -1e30f;
                }
            }

            // ---- unnormalized softmax ----
#pragma unroll
            for (int nt = 0; nt < 8; nt++) {
                s[nt][0] = ex2f(s[nt][0]);
                s[nt][1] = ex2f(s[nt][1]);
                s[nt][2] = ex2f(s[nt][2]);
                s[nt][3] = ex2f(s[nt][3]);
                l0 += s[nt][0] + s[nt][1];
                l1 += s[nt][2] + s[nt][3];
            }

            // ---- O += P @ V ----
#pragma unroll
            for (int kt = 0; kt < 4; kt++) {
                uint32_t ah[4];
                ah[0] = pk(s[2 * kt][0],     s[2 * kt][1]);
                ah[1] = pk(s[2 * kt][2],     s[2 * kt][3]);
                ah[2] = pk(s[2 * kt + 1][0], s[2 * kt + 1][1]);
                ah[3] = pk(s[2 * kt + 1][2], s[2 * kt + 1][3]);
#pragma unroll
                for (int nh = 0; nh < 4; nh++) {
                    uint32_t bh[4];
                    LDSM4T(bh, bufv + vro + (uint32_t)(kt * 2048) + vx[nh]);
                    MMAH(o[2 * nh],     ah, bh[0], bh[1]);
                    MMAH(o[2 * nh + 1], ah, bh[2], bh[3]);
                }
            }
        }
    }

    // ---- single row-sum reduction at the end ----
    l0 += __shfl_xor_sync(0xffffffffu, l0, 1);
    l0 += __shfl_xor_sync(0xffffffffu, l0, 2);
    l1 += __shfl_xor_sync(0xffffffffu, l1, 1);
    l1 += __shfl_xor_sync(0xffffffffu, l1, 2);

    // ---- normalize + write ----
    const float inv0 = 1.f / l0, inv1 = 1.f / l1;
    float* o1 = out + ((size_t)b * Tt + r1g) * Hh + 2 * tig;
    float* o2 = out + ((size_t)b * Tt + r2g) * Hh + 2 * tig;
#pragma unroll
    for (int nt = 0; nt < 8; nt++) {
        *(float2*)(o1 + 8 * nt) = make_float2(o[nt][0] * inv0, o[nt][1] * inv0);
        *(float2*)(o2 + 8 * nt) = make_float2(o[nt][2] * inv1, o[nt][3] * inv1);
    }
}

// ---------------------------------------------------------------------------
// Harness entry
// ---------------------------------------------------------------------------
extern "C" void kernel_launch(void* const* d_in, const int* in_sizes, int n_in,
                              void* d_out, int out_size)
{
    const float* x  = (const float*)d_in[0];
    const float* Wk = (const float*)d_in[1];
    const float* Wq = (const float*)d_in[2];
    const float* Wv = (const float*)d_in[3];
    float* out = (float*)d_out;

    cudaFuncSetAttribute(proj_tc, cudaFuncAttributeMaxDynamicSharedMemorySize, PJ_SMEM);
    cudaFuncSetAttribute(attn_tc, cudaFuncAttributeMaxDynamicSharedMemorySize, AT_SMEM);

    prep_w<<<768, 256>>>(Wk, Wq, Wv);
    proj_tc<<<BT / 64, 256, PJ_SMEM>>>(x);
    attn_tc<<<dim3(Tt / 64, Bb), 128, AT_SMEM>>>(out);
}

// round 16
// speedup vs baseline: 1.0349x; 1.0349x over previous
#include <cuda_runtime.h>
#include <cuda_fp16.h>
#include <cstdint>

// Problem constants
#define Bb 32
#define Tt 2048
#define Cc 1024
#define Hh 64
#define BT (Bb * Tt)

// 0.125 (= H^-0.5) * log2(e): scores computed directly in base-2 domain
#define QSCALE 0.180336880111227f

// Scratch (__device__ globals; no allocation allowed)
__device__ __half g_Wh[(size_t)Cc * 192];     // [k][n]  n: 0..63 K, 64..127 Q, 128..191 V
__device__ __half g_q[(size_t)BT * Hh];
__device__ __half g_k[(size_t)BT * Hh];
__device__ __half g_v[(size_t)BT * Hh];

// ---------------------------------------------------------------------------
// Helpers
// ---------------------------------------------------------------------------
__device__ __forceinline__ uint32_t pk(float a, float b) {
    __half2 h = __floats2half2_rn(a, b);
    return *(uint32_t*)&h;
}

// pack two fp32 scores to half2, then 2-way MUFU exp2 -> packed fp16 P
__device__ __forceinline__ uint32_t ex2h2(float a, float b) {
    uint32_t u = pk(a, b), r;
    asm("ex2.approx.f16x2 %0, %1;" : "=r"(r) : "r"(u));
    return r;
}

__device__ __forceinline__ uint32_t smem_u32(const void* p) {
    uint32_t a;
    asm("{ .reg .u64 t; cvta.to.shared.u64 t, %1; cvt.u32.u64 %0, t; }" : "=r"(a) : "l"(p));
    return a;
}

#define LDSM4(r, addr) \
    asm volatile("ldmatrix.sync.aligned.m8n8.x4.shared.b16 {%0,%1,%2,%3}, [%4];" \
        : "=r"((r)[0]), "=r"((r)[1]), "=r"((r)[2]), "=r"((r)[3]) : "r"(addr))
#define LDSM4T(r, addr) \
    asm volatile("ldmatrix.sync.aligned.m8n8.x4.trans.shared.b16 {%0,%1,%2,%3}, [%4];" \
        : "=r"((r)[0]), "=r"((r)[1]), "=r"((r)[2]), "=r"((r)[3]) : "r"(addr))
#define MMAH(d, a, b0_, b1_) \
    asm volatile("mma.sync.aligned.m16n8k16.row.col.f32.f16.f16.f32 " \
        "{%0,%1,%2,%3}, {%4,%5,%6,%7}, {%8,%9}, {%0,%1,%2,%3};" \
        : "+f"((d)[0]), "+f"((d)[1]), "+f"((d)[2]), "+f"((d)[3]) \
        : "r"((a)[0]), "r"((a)[1]), "r"((a)[2]), "r"((a)[3]), "r"(b0_), "r"(b1_))
#define CP_ASYNC16(dst, src) \
    asm volatile("cp.async.cg.shared.global [%0], [%1], 16;" :: "r"(dst), "l"(src))
#define CP_COMMIT() asm volatile("cp.async.commit_group;" ::: "memory")
#define CP_WAIT(n)  asm volatile("cp.async.wait_group %0;" :: "n"(n) : "memory")

// ---------------------------------------------------------------------------
// Prep: W -> fp16, Q scale folded, layout [k=1024][n=192]
// ---------------------------------------------------------------------------
__global__ __launch_bounds__(256) void prep_w(
    const float* __restrict__ Wk, const float* __restrict__ Wq, const float* __restrict__ Wv)
{
    const int idx = blockIdx.x * 256 + threadIdx.x;
    const int k = idx / 192, n = idx % 192;
    float f;
    if (n < 64)       f = Wk[k * 64 + n];
    else if (n < 128) f = Wq[k * 64 + (n - 64)] * QSCALE;
    else              f = Wv[k * 64 + (n - 128)];
    g_Wh[idx] = __float2half_rn(f);
}

// ---------------------------------------------------------------------------
// Projection GEMM (EXACT R12 version): fp16, 64x192 CTA tile, 2 CTAs/SM,
// distance-2 x prefetch in registers, W cp.async double-buffered.
// ---------------------------------------------------------------------------
#define SA_BUF   8192
#define SB_OFF   16384
#define SB_BUF   25600
#define BSTRIDE  400
#define PJ_SMEM  67584

#define LDG_X(C0) do { \
    const float* _xs = x + (size_t)row0 * Cc + (C0) + (tid & 15) * 4; \
    _Pragma("unroll") for (int _i = 0; _i < 4; _i++) \
        xr[_i] = *(const float4*)(_xs + (size_t)(_i * 16 + (tid >> 4)) * Cc); \
} while (0)

#define CONVERT_X(P) do { \
    _Pragma("unroll") for (int _i = 0; _i < 4; _i++) { \
        const int _r = _i * 16 + (tid >> 4); \
        const int _c4 = tid & 15; \
        uint2 _hv; \
        _hv.x = pk(xr[_i].x, xr[_i].y); \
        _hv.y = pk(xr[_i].z, xr[_i].w); \
        const uint32_t _off = (uint32_t)(_r * 128 + (((_c4 >> 1) ^ (_r & 7)) << 4) + (_c4 & 1) * 8); \
        *(uint2*)(smp + (P) * SA_BUF + _off) = _hv; \
    } \
} while (0)

#define W_LOAD(C) do { \
    const uint32_t _bw = sb + SB_OFF + ((C) & 1) * SB_BUF; \
    _Pragma("unroll") for (int _i = 0; _i < 6; _i++) { \
        const int _u = _i * 256 + tid; \
        const int _r = _u / 24, _cg = _u % 24; \
        CP_ASYNC16(_bw + _r * BSTRIDE + _cg * 16, \
                   (const char*)(g_Wh + (size_t)((C) * 64 + _r) * 192 + _cg * 8)); \
    } \
    CP_COMMIT(); \
} while (0)

__global__ __launch_bounds__(256, 2) void proj_tc(const float* __restrict__ x)
{
    extern __shared__ char smp[];
    const uint32_t sb = smem_u32(smp);
    const int tid  = threadIdx.x;
    const int wid  = tid >> 5;
    const int lane = tid & 31;
    const int wm   = wid >> 2;
    const int wn   = wid & 3;
    const int row0 = blockIdx.x * 64;

    const int gid = lane >> 2, tig = lane & 3;
    const int lr  = lane & 7,  grp = lane >> 3;

    float acc[2][6][4];
#pragma unroll
    for (int mi = 0; mi < 2; mi++)
#pragma unroll
        for (int j = 0; j < 6; j++)
#pragma unroll
            for (int e = 0; e < 4; e++) acc[mi][j][e] = 0.f;

    int rowA[2];
#pragma unroll
    for (int mi = 0; mi < 2; mi++) rowA[mi] = wm * 32 + mi * 16 + lr + (grp & 1) * 8;
    const int ac16g = grp >> 1;
    const uint32_t bofs = (uint32_t)((lr + (grp & 1) * 8) * BSTRIDE + wn * 96 + (grp >> 1) * 16);

    float4 xr[4];

    LDG_X(0);
    W_LOAD(0);
    CONVERT_X(0);
    LDG_X(64);

    for (int c = 0; c < 16; c++) {
        const int p = c & 1;
        CP_WAIT(0);
        __syncthreads();

        const uint32_t abh  = sb + p * SA_BUF;
        const uint32_t bbuf = sb + SB_OFF + p * SB_BUF;
#pragma unroll
        for (int ks = 0; ks < 4; ks++) {
            uint32_t ah[2][4];
#pragma unroll
            for (int mi = 0; mi < 2; mi++) {
                const int c16 = 2 * ks + ac16g;
                LDSM4(ah[mi], abh + (uint32_t)(rowA[mi] * 128 + ((c16 ^ lr) << 4)));
            }
#pragma unroll
            for (int nt = 0; nt < 3; nt++) {
                uint32_t bh[4];
                LDSM4T(bh, bbuf + bofs + (uint32_t)(ks * 16 * BSTRIDE + nt * 32));
#pragma unroll
                for (int mi = 0; mi < 2; mi++) {
                    MMAH(acc[mi][2 * nt],     ah[mi], bh[0], bh[1]);
                    MMAH(acc[mi][2 * nt + 1], ah[mi], bh[2], bh[3]);
                }
            }
        }

        if (c < 15) {
            W_LOAD(c + 1);
            CONVERT_X(p ^ 1);
        }
        if (c < 14) LDG_X((c + 2) * 64);
    }

#pragma unroll
    for (int mi = 0; mi < 2; mi++) {
        const int r1 = row0 + wm * 32 + mi * 16 + gid;
        const int r2 = r1 + 8;
#pragma unroll
        for (int j = 0; j < 6; j++) {
            const int col = wn * 48 + j * 8 + tig * 2;
            __half* dst; int cc;
            if (col < 64)       { dst = g_k; cc = col; }
            else if (col < 128) { dst = g_q; cc = col - 64; }
            else                { dst = g_v; cc = col - 128; }
            *(uint32_t*)(dst + (size_t)r1 * Hh + cc) = pk(acc[mi][j][0], acc[mi][j][1]);
            *(uint32_t*)(dst + (size_t)r2 * Hh + cc) = pk(acc[mi][j][2], acc[mi][j][3]);
        }
    }
}

// ---------------------------------------------------------------------------
// Flash attention: R14 structure (64-row q-tiles, 4 warps, 4 CTAs/SM, 144B
// stride, 2-stage KV ring, Q in regs) with a leaner softmax:
//   - P = ex2.approx.f16x2 on packed half2 scores (half the MUFU ops, no
//     separate fp32->fp16 pack; masked -1e30 -> -inf -> ex2 = 0)
//   - l accumulated by an extra m16n8k16 MMA against an all-ones B fragment
//     (tensor pipe has slack) -> no per-element FADDs, no epilogue shuffles,
//     and l is the exact sum of the same fp16 P used in PV.
// ---------------------------------------------------------------------------
#define RSTRIDE 144
#define KV_OFF  9216              // Q: 64 rows x 144
#define STAGE   18432             // K 64x144 + V 64x144
#define AT_SMEM 46080             // Q + 2 stages
#define ONE2    0x3C003C00u       // half2(1.0, 1.0)

#define LOAD_KV64(J) do { \
    const int _jn = (J) * 64; \
    const uint32_t _st = sb + KV_OFF + ((J) & 1) * STAGE; \
    _Pragma("unroll") for (int _i = 0; _i < 4; _i++) { \
        const int _idx = _i * 128 + tid; \
        const int _r = _idx >> 3, _cg = _idx & 7; \
        const size_t _g = (size_t)(b * Tt + _jn + _r) * Hh + _cg * 8; \
        const uint32_t _d0 = _st + _r * RSTRIDE + _cg * 16; \
        CP_ASYNC16(_d0,        (const char*)(g_k + _g)); \
        CP_ASYNC16(_d0 + 9216, (const char*)(g_v + _g)); \
    } \
    CP_COMMIT(); \
} while (0)

__global__ __launch_bounds__(128, 4) void attn_tc(float* __restrict__ out)
{
    extern __shared__ char sma[];
    const uint32_t sb  = smem_u32(sma);
    const uint32_t sQh = sb;

    const int tid  = threadIdx.x;
    const int w    = tid >> 5;                       // 0..3
    const int lane = tid & 31;
    const int b    = blockIdx.y;
    const int it   = (Tt / 64 - 1) - blockIdx.x;     // heaviest q-tiles first
    const int q0   = it * 64;
    const int jmax = it;                             // 64-row KV tiles 0..it

    const int gid = lane >> 2, tig = lane & 3;
    const int lr  = lane & 7,  grp = lane >> 3;

    const uint32_t aQ = (uint32_t)((16 * w + lr + (grp & 1) * 8) * RSTRIDE + (grp >> 1) * 16);
    const uint32_t aK = (uint32_t)((lr + (grp >> 1) * 8) * RSTRIDE + (grp & 1) * 16);
    const uint32_t aV = (uint32_t)((lr + (grp & 1) * 8) * RSTRIDE + (grp >> 1) * 16);

    // ---- prologue: Q + KV(0) in one group ----
#pragma unroll
    for (int i = 0; i < 4; i++) {
        const int idx = i * 128 + tid;               // < 512
        const int r = idx >> 3, cg = idx & 7;
        CP_ASYNC16(sQh + r * RSTRIDE + cg * 16,
                   (const char*)(g_q + (size_t)(b * Tt + q0 + r) * Hh + cg * 8));
        const size_t g = (size_t)(b * Tt + r) * Hh + cg * 8;
        const uint32_t d0 = sb + KV_OFF + r * RSTRIDE + cg * 16;
        CP_ASYNC16(d0,        (const char*)(g_k + g));
        CP_ASYNC16(d0 + 9216, (const char*)(g_v + g));
    }
    CP_COMMIT();
    CP_WAIT(0);
    __syncthreads();

    // Q into registers for good
    uint32_t qf[4][4];
#pragma unroll
    for (int ks = 0; ks < 4; ks++) LDSM4(qf[ks], sQh + aQ + ks * 32);

    float o[8][4];
#pragma unroll
    for (int nt = 0; nt < 8; nt++)
#pragma unroll
        for (int e = 0; e < 4; e++) o[nt][e] = 0.f;
    float lacc[4] = {0.f, 0.f, 0.f, 0.f};           // P @ ones row sums (MMA)

    const int r1g = q0 + 16 * w + gid;
    const int r2g = r1g + 8;
    const int wlim = q0 + 16 * w + 15;

    for (int jt = 0; jt <= jmax; jt++) {
        if (jt > 0) {
            CP_WAIT(0);              // KV(jt) landed
            __syncthreads();         // everyone done with buffer (jt+1)&1
        }
        if (jt < jmax) LOAD_KV64(jt + 1);

        const int j0 = jt * 64;
        if (j0 <= wlim) {
            const uint32_t buf  = sb + KV_OFF + (jt & 1) * STAGE;
            const uint32_t bufv = buf + 9216;

            // ---- S = Q @ K^T ----
            float s[8][4];
#pragma unroll
            for (int nt = 0; nt < 8; nt++)
#pragma unroll
                for (int e = 0; e < 4; e++) s[nt][e] = 0.f;
#pragma unroll
            for (int ks = 0; ks < 4; ks++) {
#pragma unroll
                for (int np = 0; np < 4; np++) {
                    uint32_t bh[4];
                    LDSM4(bh, buf + aK + np * (16 * RSTRIDE) + ks * 32);
                    MMAH(s[2 * np],     qf[ks], bh[0], bh[1]);
                    MMAH(s[2 * np + 1], qf[ks], bh[2], bh[3]);
                }
            }

            // ---- causal mask (-1e30 -> half -inf -> ex2 = 0) ----
            if (j0 + 63 > q0 + 16 * w) {
#pragma unroll
                for (int nt = 0; nt < 8; nt++) {
                    const int cb = j0 + 8 * nt + 2 * tig;
                    if (cb     > r1g) s[nt][0] = -1e30f;
                    if (cb + 1 > r1g) s[nt][1] = -1e30f;
                    if (cb     > r2g) s[nt][2] = -1e30f;
                    if (cb + 1 > r2g) s[nt][3] = -1e30f;
                }
            }

            // ---- P = ex2(S) in fp16x2; l via ones-MMA; O += P @ V ----
#pragma unroll
            for (int kt = 0; kt < 4; kt++) {
                uint32_t ah[4];
                ah[0] = ex2h2(s[2 * kt][0],     s[2 * kt][1]);
                ah[1] = ex2h2(s[2 * kt][2],     s[2 * kt][3]);
                ah[2] = ex2h2(s[2 * kt + 1][0], s[2 * kt + 1][1]);
                ah[3] = ex2h2(s[2 * kt + 1][2], s[2 * kt + 1][3]);
                MMAH(lacc, ah, ONE2, ONE2);          // row sums on tensor pipe
#pragma unroll
                for (int nh = 0; nh < 4; nh++) {
                    uint32_t bh[4];
                    LDSM4T(bh, bufv + aV + kt * (16 * RSTRIDE) + nh * 32);
                    MMAH(o[2 * nh],     ah, bh[0], bh[1]);
                    MMAH(o[2 * nh + 1], ah, bh[2], bh[3]);
                }
            }
        }
    }

    // ---- normalize + write (lacc[0]=row r1 sum, lacc[2]=row r2 sum) ----
    const float inv0 = 1.f / lacc[0], inv1 = 1.f / lacc[2];
    float* o1 = out + ((size_t)b * Tt + r1g) * Hh + 2 * tig;
    float* o2 = out + ((size_t)b * Tt + r2g) * Hh + 2 * tig;
#pragma unroll
    for (int nt = 0; nt < 8; nt++) {
        *(float2*)(o1 + 8 * nt) = make_float2(o[nt][0] * inv0, o[nt][1] * inv0);
        *(float2*)(o2 + 8 * nt) = make_float2(o[nt][2] * inv1, o[nt][3] * inv1);
    }
}

// ---------------------------------------------------------------------------
// Harness entry
// ---------------------------------------------------------------------------
extern "C" void kernel_launch(void* const* d_in, const int* in_sizes, int n_in,
                              void* d_out, int out_size)
{
    const float* x  = (const float*)d_in[0];
    const float* Wk = (const float*)d_in[1];
    const float* Wq = (const float*)d_in[2];
    const float* Wv = (const float*)d_in[3];
    float* out = (float*)d_out;

    cudaFuncSetAttribute(proj_tc, cudaFuncAttributeMaxDynamicSharedMemorySize, PJ_SMEM);
    cudaFuncSetAttribute(attn_tc, cudaFuncAttributeMaxDynamicSharedMemorySize, AT_SMEM);

    prep_w<<<768, 256>>>(Wk, Wq, Wv);
    proj_tc<<<BT / 64, 256, PJ_SMEM>>>(x);
    attn_tc<<<dim3(Tt / 64, Bb), 128, AT_SMEM>>>(out);
}